// round 16
// baseline (speedup 1.0000x reference)
#include <cuda_runtime.h>
#include <cuda_fp16.h>
#include <cstdint>

#define D_MODEL   1024
#define NUM_HEADS 16
#define HEAD_DIM  64
#define BATCH     4
#define SEQ       2048
#define MTOT      (BATCH * SEQ)

// Scratch (allocation-free: __device__ globals), all fp16.
__device__ __half g_X [MTOT * D_MODEL];
__device__ __half g_Wq[D_MODEL * D_MODEL];
__device__ __half g_Wk[D_MODEL * D_MODEL];
__device__ __half g_Wv[D_MODEL * D_MODEL];
__device__ __half g_Wo[D_MODEL * D_MODEL];
__device__ __half g_Q [MTOT * D_MODEL];
__device__ __half g_K [MTOT * D_MODEL];
__device__ __half g_V [MTOT * D_MODEL];
__device__ __half g_AO[MTOT * D_MODEL];

// ---------------------------------------------------------------------------
// helpers
// ---------------------------------------------------------------------------
__device__ __forceinline__ void mma_f16(float c[4], const unsigned a[4],
                                        const unsigned b[2]) {
    asm volatile(
        "mma.sync.aligned.m16n8k16.row.col.f32.f16.f16.f32 "
        "{%0,%1,%2,%3}, {%4,%5,%6,%7}, {%8,%9}, {%0,%1,%2,%3};"
        : "+f"(c[0]), "+f"(c[1]), "+f"(c[2]), "+f"(c[3])
        : "r"(a[0]), "r"(a[1]), "r"(a[2]), "r"(a[3]), "r"(b[0]), "r"(b[1]));
}

__device__ __forceinline__ unsigned h2u(__half2 h) {
    return *reinterpret_cast<unsigned*>(&h);
}

__device__ __forceinline__ void ldsm_x4(unsigned r[4], uint32_t a) {
    asm volatile("ldmatrix.sync.aligned.m8n8.x4.shared.b16 {%0,%1,%2,%3}, [%4];"
        : "=r"(r[0]), "=r"(r[1]), "=r"(r[2]), "=r"(r[3]) : "r"(a));
}
__device__ __forceinline__ void ldsm_x4_t(unsigned r[4], uint32_t a) {
    asm volatile("ldmatrix.sync.aligned.m8n8.x4.trans.shared.b16 {%0,%1,%2,%3}, [%4];"
        : "=r"(r[0]), "=r"(r[1]), "=r"(r[2]), "=r"(r[3]) : "r"(a));
}
__device__ __forceinline__ void cp16(uint32_t dst, const void* src) {
    asm volatile("cp.async.cg.shared.global [%0], [%1], 16;" :: "r"(dst), "l"(src));
}

// ---------------------------------------------------------------------------
// fp32 -> fp16 convert, 8 elems/thread
// ---------------------------------------------------------------------------
__global__ __launch_bounds__(256)
void cvt_f32_f16_kernel(const float* __restrict__ in, __half* __restrict__ out,
                        int n8)
{
    const int i = blockIdx.x * 256 + threadIdx.x;
    if (i >= n8) return;
    const float4 a = ((const float4*)in)[i * 2];
    const float4 b = ((const float4*)in)[i * 2 + 1];
    uint4 u;
    u.x = h2u(__floats2half2_rn(a.x, a.y));
    u.y = h2u(__floats2half2_rn(a.z, a.w));
    u.z = h2u(__floats2half2_rn(b.x, b.y));
    u.w = h2u(__floats2half2_rn(b.z, b.w));
    ((uint4*)out)[i] = u;
}

// ---------------------------------------------------------------------------
// fp16 GEMM v2 (NT) — EXACT R15 version (~51 us each).
// ---------------------------------------------------------------------------
template <bool SCATTER>
__global__ __launch_bounds__(256)
void gemm_f16_kernel(const __half* __restrict__ A, const __half* __restrict__ W,
                     const float* __restrict__ bias, void* __restrict__ Cv)
{
    extern __shared__ __align__(16) __half gsm[];
    const uint32_t sm0 = (uint32_t)__cvta_generic_to_shared(gsm);

    const int K = D_MODEL;
    const int tid    = threadIdx.x;
    const int wid    = tid >> 5;
    const int lane   = tid & 31;
    const int gid    = lane >> 2;
    const int tig    = lane & 3;
    const int warp_m = wid >> 2;
    const int warp_n = wid & 3;
    const int m0     = blockIdx.y * 128;
    const int n0     = blockIdx.x * 128;

    const int rl   = lane & 7;
    const int mK   = lane >> 3;
    const int aRow = (mK & 1) * 8 + rl;
    const int aCp  = mK >> 1;
    const int bRow = ((lane >> 4) & 1) * 8 + rl;
    const int bCp  = mK & 1;

    float acc[4][4][4];
#pragma unroll
    for (int i = 0; i < 4; i++)
#pragma unroll
        for (int j = 0; j < 4; j++)
#pragma unroll
            for (int r = 0; r < 4; r++) acc[i][j][r] = 0.f;

    auto stage = [&](int buf, int k0) {
        const uint32_t ab = sm0 + (uint32_t)buf * 32768u;
        const uint32_t wb = ab + 16384u;
#pragma unroll
        for (int it = 0; it < 4; it++) {
            const int g   = tid + it * 256;
            const int r   = g >> 3;
            const int c16 = g & 7;
            const uint32_t off = (uint32_t)(r * 128 + ((c16 ^ (r & 7)) * 16));
            cp16(ab + off, A + (size_t)(m0 + r) * K + k0 + c16 * 8);
            cp16(wb + off, W + (size_t)(n0 + r) * K + k0 + c16 * 8);
        }
        asm volatile("cp.async.commit_group;");
    };

    stage(0, 0);

    const int NT = K / 64;
    for (int i = 0; i < NT; i++) {
        if (i > 0) __syncthreads();
        if (i + 1 < NT) {
            stage((i + 1) & 1, (i + 1) * 64);
            asm volatile("cp.async.wait_group 1;");
        } else {
            asm volatile("cp.async.wait_group 0;");
        }
        __syncthreads();

        const uint32_t ab = sm0 + (uint32_t)(i & 1) * 32768u;
        const uint32_t wb = ab + 16384u;

#pragma unroll
        for (int kkb = 0; kkb < 4; kkb++) {
            unsigned af[4][4];
#pragma unroll
            for (int mt = 0; mt < 4; mt++) {
                const int row = warp_m * 64 + mt * 16 + aRow;
                const int ch  = (2 * kkb + aCp) ^ rl;
                ldsm_x4(af[mt], ab + (uint32_t)(row * 128 + ch * 16));
            }
            unsigned bf[2][4];
#pragma unroll
            for (int nt2 = 0; nt2 < 2; nt2++) {
                const int row = warp_n * 32 + nt2 * 16 + bRow;
                const int ch  = (2 * kkb + bCp) ^ rl;
                ldsm_x4(bf[nt2], wb + (uint32_t)(row * 128 + ch * 16));
            }
#pragma unroll
            for (int mt = 0; mt < 4; mt++)
#pragma unroll
                for (int nt2 = 0; nt2 < 2; nt2++) {
                    mma_f16(acc[mt][2 * nt2],     af[mt], bf[nt2]);
                    mma_f16(acc[mt][2 * nt2 + 1], af[mt], bf[nt2] + 2);
                }
        }
    }

#pragma unroll
    for (int nt = 0; nt < 4; nt++) {
        const int n  = n0 + warp_n * 32 + nt * 8 + tig * 2;
        const float b0 = bias[n], b1 = bias[n + 1];
#pragma unroll
        for (int mt = 0; mt < 4; mt++) {
            const int m = m0 + warp_m * 64 + mt * 16 + gid;
            if (SCATTER) {
                __half* Ch = (__half*)Cv;
                const int h  = n >> 6;
                const int hd = n & 63;
                const int bb = m >> 11;
                const int s  = m & (SEQ - 1);
                unsigned u0 = h2u(__floats2half2_rn(acc[mt][nt][0] + b0,
                                                    acc[mt][nt][1] + b1));
                unsigned u1 = h2u(__floats2half2_rn(acc[mt][nt][2] + b0,
                                                    acc[mt][nt][3] + b1));
                *(unsigned*)(Ch + ((size_t)((bb * NUM_HEADS + h) * SEQ + s))     * HEAD_DIM + hd) = u0;
                *(unsigned*)(Ch + ((size_t)((bb * NUM_HEADS + h) * SEQ + s + 8)) * HEAD_DIM + hd) = u1;
            } else {
                float* Cf = (float*)Cv;
                float2 v0 = make_float2(acc[mt][nt][0] + b0, acc[mt][nt][1] + b1);
                float2 v1 = make_float2(acc[mt][nt][2] + b0, acc[mt][nt][3] + b1);
                *(float2*)(Cf + (size_t)m * D_MODEL + n)       = v0;
                *(float2*)(Cf + (size_t)(m + 8) * D_MODEL + n) = v1;
            }
        }
    }
}

// ---------------------------------------------------------------------------
// Flash attention v9: R14 pipeline + f16x2 exp softmax.
// exp computed as h2exp2 on packed (s - m) pairs -> one MUFU op per 2 values,
// results ARE the PV A-fragments (no separate pack). l summed in fp32.
// ---------------------------------------------------------------------------
#define FA_SMEM 65536

__global__ __launch_bounds__(256, 1)
void flash_attn_f16_kernel(const __half* __restrict__ Q, const __half* __restrict__ K,
                           const __half* __restrict__ V, __half* __restrict__ AO)
{
    extern __shared__ __align__(16) __half smh[];
    const uint32_t sm0 = (uint32_t)__cvta_generic_to_shared(smh);

    const int tid  = threadIdx.x;
    const int w    = tid >> 5;
    const int lane = tid & 31;
    const int gid  = lane >> 2;
    const int tig  = lane & 3;
    const int bh   = blockIdx.y;
    const int q0   = blockIdx.x * 128;
    const float qscale = 0.125f * 1.44269504088896340736f;  // Hd^-0.5 * log2e

    const __half* Qb = Q + (size_t)bh * SEQ * HEAD_DIM;
    const __half* Kb = K + (size_t)bh * SEQ * HEAD_DIM;
    const __half* Vb = V + (size_t)bh * SEQ * HEAD_DIM;

    // ---- Q A-fragments in registers ----
    unsigned qf[4][4];
    {
        const __half* q0p = Qb + (size_t)(q0 + w * 16 + gid) * HEAD_DIM;
        const __half* q1p = q0p + 8 * HEAD_DIM;
#pragma unroll
        for (int kkb = 0; kkb < 4; kkb++) {
            const int c = kkb * 16 + 2 * tig;
#pragma unroll
            for (int j = 0; j < 4; j++) {
                const __half* p = (j & 1) ? q1p : q0p;
                const int col  = c + (j >> 1) * 8;
                unsigned raw = *(const unsigned*)(p + col);
                float2 f = __half22float2(*reinterpret_cast<__half2*>(&raw));
                qf[kkb][j] = h2u(__floats2half2_rn(f.x * qscale, f.y * qscale));
            }
        }
    }

    // lane constants for ldmatrix addressing
    const int rl   = lane & 7;
    const int mK   = lane >> 3;
    const int K_cp = mK & 1;
    const int kRow = (((lane >> 4) & 1) * 8 + rl) * 128;
    const int vKv  = (mK & 1) * 8 + rl;
    const int V_cp = mK >> 1;

    float m0v = -1e30f, m1v = -1e30f, l0 = 0.f, l1 = 0.f;
    float oacc[8][4];
#pragma unroll
    for (int nt = 0; nt < 8; nt++)
#pragma unroll
        for (int r = 0; r < 4; r++) oacc[nt][r] = 0.f;

    auto stage = [&](int buf, int kv0) {
        const uint32_t bb = sm0 + buf * 32768;
#pragma unroll
        for (int it = 0; it < 4; it++) {
            const int g   = tid + it * 256;
            const int r   = g >> 3;
            const int c16 = g & 7;
            const uint32_t off = (uint32_t)(r * 128 + ((c16 ^ (r & 7)) * 16));
            const size_t gsrc = (size_t)(kv0 + r) * HEAD_DIM + c16 * 8;
            cp16(bb + off,         Kb + gsrc);
            cp16(bb + 16384 + off, Vb + gsrc);
        }
        asm volatile("cp.async.commit_group;");
    };

    stage(0, 0);

    for (int i = 0; i < 16; i++) {
        if (i > 0) __syncthreads();
        if (i + 1 < 16) {
            stage((i + 1) & 1, (i + 1) * 128);
            asm volatile("cp.async.wait_group 1;");
        } else {
            asm volatile("cp.async.wait_group 0;");
        }
        __syncthreads();

        const uint32_t kb = sm0 + (i & 1) * 32768;
        const uint32_t vb = kb + 16384;

        // ---- S = Q K^T ----
        float sacc[16][4];
#pragma unroll
        for (int nt = 0; nt < 16; nt++)
#pragma unroll
            for (int r = 0; r < 4; r++) sacc[nt][r] = 0.f;

#pragma unroll
        for (int kkb = 0; kkb < 4; kkb++) {
            const uint32_t base = kb + kRow + (uint32_t)((((2 * kkb + K_cp) ^ rl)) * 16);
#pragma unroll
            for (int nt2 = 0; nt2 < 8; nt2++) {
                unsigned bfr[4];
                ldsm_x4(bfr, base + nt2 * 2048);
                mma_f16(sacc[2 * nt2],     qf[kkb], bfr);
                mma_f16(sacc[2 * nt2 + 1], qf[kkb], bfr + 2);
            }
        }

        // ---- online softmax (log2 domain); exp via h2exp2 (f16x2 MUFU) ----
        float rm0 = -1e30f, rm1 = -1e30f;
#pragma unroll
        for (int nt = 0; nt < 16; nt++) {
            rm0 = fmaxf(rm0, fmaxf(sacc[nt][0], sacc[nt][1]));
            rm1 = fmaxf(rm1, fmaxf(sacc[nt][2], sacc[nt][3]));
        }
        rm0 = fmaxf(rm0, __shfl_xor_sync(0xffffffffu, rm0, 1));
        rm0 = fmaxf(rm0, __shfl_xor_sync(0xffffffffu, rm0, 2));
        rm1 = fmaxf(rm1, __shfl_xor_sync(0xffffffffu, rm1, 1));
        rm1 = fmaxf(rm1, __shfl_xor_sync(0xffffffffu, rm1, 2));

        const float mn0 = fmaxf(m0v, rm0);
        const float mn1 = fmaxf(m1v, rm1);
        const float al0 = exp2f(m0v - mn0);
        const float al1 = exp2f(m1v - mn1);
        m0v = mn0; m1v = mn1;

        float rs0 = 0.f, rs1 = 0.f;
        unsigned pe[16][2];      // exp'd P in PV A-fragment layout
#pragma unroll
        for (int nt = 0; nt < 16; nt++) {
            __half2 a0 = __floats2half2_rn(sacc[nt][0] - mn0, sacc[nt][1] - mn0);
            __half2 a1 = __floats2half2_rn(sacc[nt][2] - mn1, sacc[nt][3] - mn1);
            __half2 e0 = h2exp2(a0);
            __half2 e1 = h2exp2(a1);
            pe[nt][0] = h2u(e0);
            pe[nt][1] = h2u(e1);
            float2 f0 = __half22float2(e0);
            float2 f1 = __half22float2(e1);
            rs0 += f0.x + f0.y;
            rs1 += f1.x + f1.y;
        }
        rs0 += __shfl_xor_sync(0xffffffffu, rs0, 1);
        rs0 += __shfl_xor_sync(0xffffffffu, rs0, 2);
        rs1 += __shfl_xor_sync(0xffffffffu, rs1, 1);
        rs1 += __shfl_xor_sync(0xffffffffu, rs1, 2);
        l0 = l0 * al0 + rs0;
        l1 = l1 * al1 + rs1;

#pragma unroll
        for (int nt = 0; nt < 8; nt++) {
            oacc[nt][0] *= al0; oacc[nt][1] *= al0;
            oacc[nt][2] *= al1; oacc[nt][3] *= al1;
        }

        // ---- O += P V : A-fragments come straight from pe ----
#pragma unroll
        for (int kkb = 0; kkb < 8; kkb++) {
            unsigned ap[4];
            ap[0] = pe[2 * kkb][0];
            ap[1] = pe[2 * kkb][1];
            ap[2] = pe[2 * kkb + 1][0];
            ap[3] = pe[2 * kkb + 1][1];
            const uint32_t vrow = vb + (uint32_t)(vKv * 128 + kkb * 2048);
#pragma unroll
            for (int h2 = 0; h2 < 4; h2++) {
                unsigned bfr[4];
                ldsm_x4_t(bfr, vrow + (uint32_t)((((2 * h2 + V_cp) ^ rl)) * 16));
                mma_f16(oacc[2 * h2],     ap, bfr);
                mma_f16(oacc[2 * h2 + 1], ap, bfr + 2);
            }
        }
    }

    // Epilogue: normalize, write fp16 [B,S,D]
    const int r0l = w * 16 + gid;
    const int b = bh >> 4;
    const int h = bh & 15;
    const float inv0 = 1.0f / l0;
    const float inv1 = 1.0f / l1;
#pragma unroll
    for (int nt = 0; nt < 8; nt++) {
        const int col = h * HEAD_DIM + nt * 8 + 2 * tig;
        unsigned u0 = h2u(__floats2half2_rn(oacc[nt][0] * inv0, oacc[nt][1] * inv0));
        unsigned u1 = h2u(__floats2half2_rn(oacc[nt][2] * inv1, oacc[nt][3] * inv1));
        *(unsigned*)(AO + (size_t)(b * SEQ + q0 + r0l)     * D_MODEL + col) = u0;
        *(unsigned*)(AO + (size_t)(b * SEQ + q0 + r0l + 8) * D_MODEL + col) = u1;
    }
}

// ---------------------------------------------------------------------------
extern "C" void kernel_launch(void* const* d_in, const int* in_sizes, int n_in,
                              void* d_out, int out_size)
{
    const float* x  = (const float*)d_in[0];
    const float* wq = (const float*)d_in[1];
    const float* bq = (const float*)d_in[2];
    const float* wk = (const float*)d_in[3];
    const float* bk = (const float*)d_in[4];
    const float* wv = (const float*)d_in[5];
    const float* bv = (const float*)d_in[6];
    const float* wo = (const float*)d_in[7];
    const float* bo = (const float*)d_in[8];

    __half *Xp, *Wqp, *Wkp, *Wvp, *Wop, *Qp, *Kp, *Vp, *AOp;
    cudaGetSymbolAddress((void**)&Xp,  g_X);
    cudaGetSymbolAddress((void**)&Wqp, g_Wq);
    cudaGetSymbolAddress((void**)&Wkp, g_Wk);
    cudaGetSymbolAddress((void**)&Wvp, g_Wv);
    cudaGetSymbolAddress((void**)&Wop, g_Wo);
    cudaGetSymbolAddress((void**)&Qp,  g_Q);
    cudaGetSymbolAddress((void**)&Kp,  g_K);
    cudaGetSymbolAddress((void**)&Vp,  g_V);
    cudaGetSymbolAddress((void**)&AOp, g_AO);

    const int xW8 = MTOT * D_MODEL / 8;
    const int wW8 = D_MODEL * D_MODEL / 8;
    cvt_f32_f16_kernel<<<(xW8 + 255) / 256, 256>>>(x,  Xp,  xW8);
    cvt_f32_f16_kernel<<<(wW8 + 255) / 256, 256>>>(wq, Wqp, wW8);
    cvt_f32_f16_kernel<<<(wW8 + 255) / 256, 256>>>(wk, Wkp, wW8);
    cvt_f32_f16_kernel<<<(wW8 + 255) / 256, 256>>>(wv, Wvp, wW8);
    cvt_f32_f16_kernel<<<(wW8 + 255) / 256, 256>>>(wo, Wop, wW8);

    const dim3 pg(D_MODEL / 128, MTOT / 128);   // (8, 64)
    const int GEMM_SMEM = 65536;
    cudaFuncSetAttribute(gemm_f16_kernel<true>,
                         cudaFuncAttributeMaxDynamicSharedMemorySize, GEMM_SMEM);
    cudaFuncSetAttribute(gemm_f16_kernel<false>,
                         cudaFuncAttributeMaxDynamicSharedMemorySize, GEMM_SMEM);

    gemm_f16_kernel<true><<<pg, 256, GEMM_SMEM>>>(Xp, Wqp, bq, Qp);
    gemm_f16_kernel<true><<<pg, 256, GEMM_SMEM>>>(Xp, Wkp, bk, Kp);
    gemm_f16_kernel<true><<<pg, 256, GEMM_SMEM>>>(Xp, Wvp, bv, Vp);

    cudaFuncSetAttribute(flash_attn_f16_kernel,
                         cudaFuncAttributeMaxDynamicSharedMemorySize, FA_SMEM);
    flash_attn_f16_kernel<<<dim3(SEQ / 128, BATCH * NUM_HEADS), 256, FA_SMEM>>>(Qp, Kp, Vp, AOp);

    gemm_f16_kernel<false><<<pg, 256, GEMM_SMEM>>>(AOp, Wop, bo, d_out);
}

// round 17
// speedup vs baseline: 1.1243x; 1.1243x over previous
#include <cuda_runtime.h>
#include <cuda_fp16.h>
#include <cstdint>

#define D_MODEL   1024
#define NUM_HEADS 16
#define HEAD_DIM  64
#define BATCH     4
#define SEQ       2048
#define MTOT      (BATCH * SEQ)

// Scratch (allocation-free: __device__ globals), all fp16.
__device__ __half g_X   [MTOT * D_MODEL];
__device__ __half g_Wqkv[3 * D_MODEL * D_MODEL];   // Wq | Wk | Wv rows
__device__ __half g_Wo  [D_MODEL * D_MODEL];
__device__ __half g_Q   [MTOT * D_MODEL];
__device__ __half g_K   [MTOT * D_MODEL];
__device__ __half g_V   [MTOT * D_MODEL];
__device__ __half g_AO  [MTOT * D_MODEL];

// ---------------------------------------------------------------------------
// helpers
// ---------------------------------------------------------------------------
__device__ __forceinline__ void mma_f16(float c[4], const unsigned a[4],
                                        const unsigned b[2]) {
    asm volatile(
        "mma.sync.aligned.m16n8k16.row.col.f32.f16.f16.f32 "
        "{%0,%1,%2,%3}, {%4,%5,%6,%7}, {%8,%9}, {%0,%1,%2,%3};"
        : "+f"(c[0]), "+f"(c[1]), "+f"(c[2]), "+f"(c[3])
        : "r"(a[0]), "r"(a[1]), "r"(a[2]), "r"(a[3]), "r"(b[0]), "r"(b[1]));
}

__device__ __forceinline__ unsigned h2u(__half2 h) {
    return *reinterpret_cast<unsigned*>(&h);
}

__device__ __forceinline__ void ldsm_x4(unsigned r[4], uint32_t a) {
    asm volatile("ldmatrix.sync.aligned.m8n8.x4.shared.b16 {%0,%1,%2,%3}, [%4];"
        : "=r"(r[0]), "=r"(r[1]), "=r"(r[2]), "=r"(r[3]) : "r"(a));
}
__device__ __forceinline__ void ldsm_x4_t(unsigned r[4], uint32_t a) {
    asm volatile("ldmatrix.sync.aligned.m8n8.x4.trans.shared.b16 {%0,%1,%2,%3}, [%4];"
        : "=r"(r[0]), "=r"(r[1]), "=r"(r[2]), "=r"(r[3]) : "r"(a));
}
__device__ __forceinline__ void cp16(uint32_t dst, const void* src) {
    asm volatile("cp.async.cg.shared.global [%0], [%1], 16;" :: "r"(dst), "l"(src));
}

// ---------------------------------------------------------------------------
// fp32 -> fp16 convert, 8 elems/thread
// ---------------------------------------------------------------------------
__global__ __launch_bounds__(256)
void cvt_f32_f16_kernel(const float* __restrict__ in, __half* __restrict__ out,
                        int n8)
{
    const int i = blockIdx.x * 256 + threadIdx.x;
    if (i >= n8) return;
    const float4 a = ((const float4*)in)[i * 2];
    const float4 b = ((const float4*)in)[i * 2 + 1];
    uint4 u;
    u.x = h2u(__floats2half2_rn(a.x, a.y));
    u.y = h2u(__floats2half2_rn(a.z, a.w));
    u.z = h2u(__floats2half2_rn(b.x, b.y));
    u.w = h2u(__floats2half2_rn(b.z, b.w));
    ((uint4*)out)[i] = u;
}

// ---------------------------------------------------------------------------
// fp16 GEMM core (validated R15 pipeline). Two instantiations:
//   QKV=true : W = concat [3*D, D], n0 in [0,3072); picks mat by n0>>10 and
//              scatters fp16 to the mat's [B,H,S,Hd] buffer.
//   QKV=false: plain C[M,N] fp32 = A @ W^T + bias  (output projection).
// ---------------------------------------------------------------------------
template <bool QKV>
__global__ __launch_bounds__(256)
void gemm_f16_kernel(const __half* __restrict__ A, const __half* __restrict__ W,
                     const float* __restrict__ bq, const float* __restrict__ bk,
                     const float* __restrict__ bv,
                     __half* __restrict__ Cq, __half* __restrict__ Ck,
                     __half* __restrict__ Cvv, float* __restrict__ Cf)
{
    extern __shared__ __align__(16) __half gsm[];
    const uint32_t sm0 = (uint32_t)__cvta_generic_to_shared(gsm);

    const int K = D_MODEL;
    const int tid    = threadIdx.x;
    const int wid    = tid >> 5;
    const int lane   = tid & 31;
    const int gid    = lane >> 2;
    const int tig    = lane & 3;
    const int warp_m = wid >> 2;
    const int warp_n = wid & 3;
    const int m0     = blockIdx.y * 128;
    const int n0     = blockIdx.x * 128;

    // per-block matrix select (n0 is 128-aligned; 1024 cols per matrix)
    const int mat = QKV ? (n0 >> 10) : 0;
    const float* bias = QKV ? (mat == 0 ? bq : (mat == 1 ? bk : bv)) : bq;
    __half* Ch = QKV ? (mat == 0 ? Cq : (mat == 1 ? Ck : Cvv)) : (__half*)0;

    const int rl   = lane & 7;
    const int mK   = lane >> 3;
    const int aRow = (mK & 1) * 8 + rl;
    const int aCp  = mK >> 1;
    const int bRow = ((lane >> 4) & 1) * 8 + rl;
    const int bCp  = mK & 1;

    float acc[4][4][4];
#pragma unroll
    for (int i = 0; i < 4; i++)
#pragma unroll
        for (int j = 0; j < 4; j++)
#pragma unroll
            for (int r = 0; r < 4; r++) acc[i][j][r] = 0.f;

    auto stage = [&](int buf, int k0) {
        const uint32_t ab = sm0 + (uint32_t)buf * 32768u;
        const uint32_t wb = ab + 16384u;
#pragma unroll
        for (int it = 0; it < 4; it++) {
            const int g   = tid + it * 256;
            const int r   = g >> 3;
            const int c16 = g & 7;
            const uint32_t off = (uint32_t)(r * 128 + ((c16 ^ (r & 7)) * 16));
            cp16(ab + off, A + (size_t)(m0 + r) * K + k0 + c16 * 8);
            cp16(wb + off, W + (size_t)(n0 + r) * K + k0 + c16 * 8);
        }
        asm volatile("cp.async.commit_group;");
    };

    stage(0, 0);

    const int NT = K / 64;
    for (int i = 0; i < NT; i++) {
        if (i > 0) __syncthreads();
        if (i + 1 < NT) {
            stage((i + 1) & 1, (i + 1) * 64);
            asm volatile("cp.async.wait_group 1;");
        } else {
            asm volatile("cp.async.wait_group 0;");
        }
        __syncthreads();

        const uint32_t ab = sm0 + (uint32_t)(i & 1) * 32768u;
        const uint32_t wb = ab + 16384u;

#pragma unroll
        for (int kkb = 0; kkb < 4; kkb++) {
            unsigned af[4][4];
#pragma unroll
            for (int mt = 0; mt < 4; mt++) {
                const int row = warp_m * 64 + mt * 16 + aRow;
                const int ch  = (2 * kkb + aCp) ^ rl;
                ldsm_x4(af[mt], ab + (uint32_t)(row * 128 + ch * 16));
            }
            unsigned bf[2][4];
#pragma unroll
            for (int nt2 = 0; nt2 < 2; nt2++) {
                const int row = warp_n * 32 + nt2 * 16 + bRow;
                const int ch  = (2 * kkb + bCp) ^ rl;
                ldsm_x4(bf[nt2], wb + (uint32_t)(row * 128 + ch * 16));
            }
#pragma unroll
            for (int mt = 0; mt < 4; mt++)
#pragma unroll
                for (int nt2 = 0; nt2 < 2; nt2++) {
                    mma_f16(acc[mt][2 * nt2],     af[mt], bf[nt2]);
                    mma_f16(acc[mt][2 * nt2 + 1], af[mt], bf[nt2] + 2);
                }
        }
    }

#pragma unroll
    for (int nt = 0; nt < 4; nt++) {
        const int n    = n0 + warp_n * 32 + nt * 8 + tig * 2;
        const int nloc = QKV ? (n & 1023) : n;
        const float b0 = bias[nloc], b1 = bias[nloc + 1];
#pragma unroll
        for (int mt = 0; mt < 4; mt++) {
            const int m = m0 + warp_m * 64 + mt * 16 + gid;
            if (QKV) {
                const int h  = nloc >> 6;
                const int hd = nloc & 63;
                const int bb = m >> 11;
                const int s  = m & (SEQ - 1);
                unsigned u0 = h2u(__floats2half2_rn(acc[mt][nt][0] + b0,
                                                    acc[mt][nt][1] + b1));
                unsigned u1 = h2u(__floats2half2_rn(acc[mt][nt][2] + b0,
                                                    acc[mt][nt][3] + b1));
                *(unsigned*)(Ch + ((size_t)((bb * NUM_HEADS + h) * SEQ + s))     * HEAD_DIM + hd) = u0;
                *(unsigned*)(Ch + ((size_t)((bb * NUM_HEADS + h) * SEQ + s + 8)) * HEAD_DIM + hd) = u1;
            } else {
                float2 v0 = make_float2(acc[mt][nt][0] + b0, acc[mt][nt][1] + b1);
                float2 v1 = make_float2(acc[mt][nt][2] + b0, acc[mt][nt][3] + b1);
                *(float2*)(Cf + (size_t)m * D_MODEL + n)       = v0;
                *(float2*)(Cf + (size_t)(m + 8) * D_MODEL + n) = v1;
            }
        }
    }
}

// ---------------------------------------------------------------------------
// Flash attention v10: R15-validated pipeline (fp32 exp2f softmax), Bc=64,
// 2 CTAs/SM (32 KB smem, __launch_bounds__(256,2) to cap regs).
// Br = 128, 8 warps; warp w owns S rows [16w, 16w+16) x 64 kv cols per tile.
// ---------------------------------------------------------------------------
#define FA_SMEM 32768

__global__ __launch_bounds__(256, 2)
void flash_attn_f16_kernel(const __half* __restrict__ Q, const __half* __restrict__ K,
                           const __half* __restrict__ V, __half* __restrict__ AO)
{
    extern __shared__ __align__(16) __half smh[];
    const uint32_t sm0 = (uint32_t)__cvta_generic_to_shared(smh);

    const int tid  = threadIdx.x;
    const int w    = tid >> 5;
    const int lane = tid & 31;
    const int gid  = lane >> 2;
    const int tig  = lane & 3;
    const int bh   = blockIdx.y;
    const int q0   = blockIdx.x * 128;
    const float qscale = 0.125f * 1.44269504088896340736f;  // Hd^-0.5 * log2e

    const __half* Qb = Q + (size_t)bh * SEQ * HEAD_DIM;
    const __half* Kb = K + (size_t)bh * SEQ * HEAD_DIM;
    const __half* Vb = V + (size_t)bh * SEQ * HEAD_DIM;

    // ---- Q A-fragments in registers ----
    unsigned qf[4][4];
    {
        const __half* q0p = Qb + (size_t)(q0 + w * 16 + gid) * HEAD_DIM;
        const __half* q1p = q0p + 8 * HEAD_DIM;
#pragma unroll
        for (int kkb = 0; kkb < 4; kkb++) {
            const int c = kkb * 16 + 2 * tig;
#pragma unroll
            for (int j = 0; j < 4; j++) {
                const __half* p = (j & 1) ? q1p : q0p;
                const int col  = c + (j >> 1) * 8;
                unsigned raw = *(const unsigned*)(p + col);
                float2 f = __half22float2(*reinterpret_cast<__half2*>(&raw));
                qf[kkb][j] = h2u(__floats2half2_rn(f.x * qscale, f.y * qscale));
            }
        }
    }

    // lane constants for ldmatrix addressing
    const int rl   = lane & 7;
    const int mK   = lane >> 3;
    const int K_cp = mK & 1;
    const int kRow = (((lane >> 4) & 1) * 8 + rl) * 128;
    const int vKv  = (mK & 1) * 8 + rl;
    const int V_cp = mK >> 1;

    float m0v = -1e30f, m1v = -1e30f, l0 = 0.f, l1 = 0.f;
    float oacc[8][4];
#pragma unroll
    for (int nt = 0; nt < 8; nt++)
#pragma unroll
        for (int r = 0; r < 4; r++) oacc[nt][r] = 0.f;

    // staging: K tile 64x128B at buf*16384, V tile at +8192
    auto stage = [&](int buf, int kv0) {
        const uint32_t bb = sm0 + (uint32_t)buf * 16384u;
#pragma unroll
        for (int it = 0; it < 2; it++) {
            const int g   = tid + it * 256;      // 0..511
            const int r   = g >> 3;              // 0..63
            const int c16 = g & 7;
            const uint32_t off = (uint32_t)(r * 128 + ((c16 ^ (r & 7)) * 16));
            const size_t gsrc = (size_t)(kv0 + r) * HEAD_DIM + c16 * 8;
            cp16(bb + off,        Kb + gsrc);
            cp16(bb + 8192 + off, Vb + gsrc);
        }
        asm volatile("cp.async.commit_group;");
    };

    stage(0, 0);

    const int NTI = SEQ / 64;   // 32
    for (int i = 0; i < NTI; i++) {
        if (i > 0) __syncthreads();
        if (i + 1 < NTI) {
            stage((i + 1) & 1, (i + 1) * 64);
            asm volatile("cp.async.wait_group 1;");
        } else {
            asm volatile("cp.async.wait_group 0;");
        }
        __syncthreads();

        const uint32_t kb = sm0 + (uint32_t)(i & 1) * 16384u;
        const uint32_t vb = kb + 8192u;

        // ---- S = Q K^T : 4 k16-blocks x 4 ldsm.x4 (8 m16n8 tiles / 64 cols)
        float sacc[8][4];
#pragma unroll
        for (int nt = 0; nt < 8; nt++)
#pragma unroll
            for (int r = 0; r < 4; r++) sacc[nt][r] = 0.f;

#pragma unroll
        for (int kkb = 0; kkb < 4; kkb++) {
            const uint32_t base = kb + kRow + (uint32_t)((((2 * kkb + K_cp) ^ rl)) * 16);
#pragma unroll
            for (int nt2 = 0; nt2 < 4; nt2++) {
                unsigned bfr[4];
                ldsm_x4(bfr, base + nt2 * 2048);
                mma_f16(sacc[2 * nt2],     qf[kkb], bfr);
                mma_f16(sacc[2 * nt2 + 1], qf[kkb], bfr + 2);
            }
        }

        // ---- online softmax in log2 domain (fp32, validated) ----
        float rm0 = -1e30f, rm1 = -1e30f;
#pragma unroll
        for (int nt = 0; nt < 8; nt++) {
            rm0 = fmaxf(rm0, fmaxf(sacc[nt][0], sacc[nt][1]));
            rm1 = fmaxf(rm1, fmaxf(sacc[nt][2], sacc[nt][3]));
        }
        rm0 = fmaxf(rm0, __shfl_xor_sync(0xffffffffu, rm0, 1));
        rm0 = fmaxf(rm0, __shfl_xor_sync(0xffffffffu, rm0, 2));
        rm1 = fmaxf(rm1, __shfl_xor_sync(0xffffffffu, rm1, 1));
        rm1 = fmaxf(rm1, __shfl_xor_sync(0xffffffffu, rm1, 2));

        const float mn0 = fmaxf(m0v, rm0);
        const float mn1 = fmaxf(m1v, rm1);
        const float al0 = exp2f(m0v - mn0);
        const float al1 = exp2f(m1v - mn1);
        m0v = mn0; m1v = mn1;

        float rs0 = 0.f, rs1 = 0.f;
#pragma unroll
        for (int nt = 0; nt < 8; nt++) {
            sacc[nt][0] = exp2f(sacc[nt][0] - mn0);
            sacc[nt][1] = exp2f(sacc[nt][1] - mn0);
            sacc[nt][2] = exp2f(sacc[nt][2] - mn1);
            sacc[nt][3] = exp2f(sacc[nt][3] - mn1);
            rs0 += sacc[nt][0] + sacc[nt][1];
            rs1 += sacc[nt][2] + sacc[nt][3];
        }
        rs0 += __shfl_xor_sync(0xffffffffu, rs0, 1);
        rs0 += __shfl_xor_sync(0xffffffffu, rs0, 2);
        rs1 += __shfl_xor_sync(0xffffffffu, rs1, 1);
        rs1 += __shfl_xor_sync(0xffffffffu, rs1, 2);
        l0 = l0 * al0 + rs0;
        l1 = l1 * al1 + rs1;

#pragma unroll
        for (int nt = 0; nt < 8; nt++) {
            oacc[nt][0] *= al0; oacc[nt][1] *= al0;
            oacc[nt][2] *= al1; oacc[nt][3] *= al1;
        }

        // ---- O += P V : P from registers (C->A fragment identity) ----
#pragma unroll
        for (int kkb = 0; kkb < 4; kkb++) {
            unsigned ap[4];
            ap[0] = h2u(__floats2half2_rn(sacc[2*kkb][0],   sacc[2*kkb][1]));
            ap[1] = h2u(__floats2half2_rn(sacc[2*kkb][2],   sacc[2*kkb][3]));
            ap[2] = h2u(__floats2half2_rn(sacc[2*kkb+1][0], sacc[2*kkb+1][1]));
            ap[3] = h2u(__floats2half2_rn(sacc[2*kkb+1][2], sacc[2*kkb+1][3]));
            const uint32_t vrow = vb + (uint32_t)(vKv * 128 + kkb * 2048);
#pragma unroll
            for (int h2 = 0; h2 < 4; h2++) {
                unsigned bfr[4];
                ldsm_x4_t(bfr, vrow + (uint32_t)((((2 * h2 + V_cp) ^ rl)) * 16));
                mma_f16(oacc[2 * h2],     ap, bfr);
                mma_f16(oacc[2 * h2 + 1], ap, bfr + 2);
            }
        }
    }

    // Epilogue: normalize, write fp16 [B,S,D]
    const int r0l = w * 16 + gid;
    const int b = bh >> 4;
    const int h = bh & 15;
    const float inv0 = 1.0f / l0;
    const float inv1 = 1.0f / l1;
#pragma unroll
    for (int nt = 0; nt < 8; nt++) {
        const int col = h * HEAD_DIM + nt * 8 + 2 * tig;
        unsigned u0 = h2u(__floats2half2_rn(oacc[nt][0] * inv0, oacc[nt][1] * inv0));
        unsigned u1 = h2u(__floats2half2_rn(oacc[nt][2] * inv1, oacc[nt][3] * inv1));
        *(unsigned*)(AO + (size_t)(b * SEQ + q0 + r0l)     * D_MODEL + col) = u0;
        *(unsigned*)(AO + (size_t)(b * SEQ + q0 + r0l + 8) * D_MODEL + col) = u1;
    }
}

// ---------------------------------------------------------------------------
extern "C" void kernel_launch(void* const* d_in, const int* in_sizes, int n_in,
                              void* d_out, int out_size)
{
    const float* x  = (const float*)d_in[0];
    const float* wq = (const float*)d_in[1];
    const float* bq = (const float*)d_in[2];
    const float* wk = (const float*)d_in[3];
    const float* bk = (const float*)d_in[4];
    const float* wv = (const float*)d_in[5];
    const float* bv = (const float*)d_in[6];
    const float* wo = (const float*)d_in[7];
    const float* bo = (const float*)d_in[8];

    __half *Xp, *Wqkvp, *Wop, *Qp, *Kp, *Vp, *AOp;
    cudaGetSymbolAddress((void**)&Xp,    g_X);
    cudaGetSymbolAddress((void**)&Wqkvp, g_Wqkv);
    cudaGetSymbolAddress((void**)&Wop,   g_Wo);
    cudaGetSymbolAddress((void**)&Qp,    g_Q);
    cudaGetSymbolAddress((void**)&Kp,    g_K);
    cudaGetSymbolAddress((void**)&Vp,    g_V);
    cudaGetSymbolAddress((void**)&AOp,   g_AO);

    const int xW8 = MTOT * D_MODEL / 8;
    const int wW8 = D_MODEL * D_MODEL / 8;
    cvt_f32_f16_kernel<<<(xW8 + 255) / 256, 256>>>(x,  Xp, xW8);
    cvt_f32_f16_kernel<<<(wW8 + 255) / 256, 256>>>(wq, Wqkvp,                       wW8);
    cvt_f32_f16_kernel<<<(wW8 + 255) / 256, 256>>>(wk, Wqkvp + D_MODEL * D_MODEL,   wW8);
    cvt_f32_f16_kernel<<<(wW8 + 255) / 256, 256>>>(wv, Wqkvp + 2 * D_MODEL * D_MODEL, wW8);
    cvt_f32_f16_kernel<<<(wW8 + 255) / 256, 256>>>(wo, Wop, wW8);

    const int GEMM_SMEM = 65536;
    cudaFuncSetAttribute(gemm_f16_kernel<true>,
                         cudaFuncAttributeMaxDynamicSharedMemorySize, GEMM_SMEM);
    cudaFuncSetAttribute(gemm_f16_kernel<false>,
                         cudaFuncAttributeMaxDynamicSharedMemorySize, GEMM_SMEM);

    // merged QKV: grid (24, 64)
    gemm_f16_kernel<true><<<dim3(3 * D_MODEL / 128, MTOT / 128), 256, GEMM_SMEM>>>(
        Xp, Wqkvp, bq, bk, bv, Qp, Kp, Vp, nullptr);

    cudaFuncSetAttribute(flash_attn_f16_kernel,
                         cudaFuncAttributeMaxDynamicSharedMemorySize, FA_SMEM);
    flash_attn_f16_kernel<<<dim3(SEQ / 128, BATCH * NUM_HEADS), 256, FA_SMEM>>>(Qp, Kp, Vp, AOp);

    // output projection: grid (8, 64)
    gemm_f16_kernel<false><<<dim3(D_MODEL / 128, MTOT / 128), 256, GEMM_SMEM>>>(
        AOp, Wop, bo, nullptr, nullptr, nullptr, nullptr, nullptr, (float*)d_out);
}